// round 17
// baseline (speedup 1.0000x reference)
#include <cuda_runtime.h>
#include <cuda_bf16.h>
#include <math.h>

// Problem constants
#define B    256
#define T    2048
#define D    64
#define N    128
#define LEAK 0.5f

// ---------------------------------------------------------------------------
// XLA ElementalIrEmitter::EmitTanh replica — VERIFIED BITWISE vs reference.
// q-polynomial first so ptxas can launch the divide's RCP during the p-chain.
// ---------------------------------------------------------------------------
__device__ __forceinline__ float tanh_xla(float x) {
    const float kClamp = 7.99881172180175781f;
    const float kTiny  = 0.0004f;
    float cx = fminf(fmaxf(x, -kClamp), kClamp);
    float x2 = __fmul_rn(cx, cx);
    float q = 1.19825839466702e-06f;
    q = __fmaf_rn(x2, q, 1.18534705686654e-04f);
    q = __fmaf_rn(x2, q, 2.26843463243900e-03f);
    q = __fmaf_rn(x2, q, 4.89352518554385e-03f);
    float p = -2.76076847742355e-16f;
    p = __fmaf_rn(x2, p, 2.00018790482477e-13f);
    p = __fmaf_rn(x2, p, -8.60467152213735e-11f);
    p = __fmaf_rn(x2, p, 5.12229709037114e-08f);
    p = __fmaf_rn(x2, p, 1.48572235717979e-05f);
    p = __fmaf_rn(x2, p, 6.37261928875436e-04f);
    p = __fmaf_rn(x2, p, 4.89352455891786e-03f);
    p = __fmul_rn(cx, p);
    float r = __fdiv_rn(p, q);
    return (fabsf(x) < kTiny) ? x : r;
}

// per-group named barriers (group g = 0/1)
#define BAR_ALL(g)  asm volatile("bar.sync %0, 192;" :: "r"(4 + (g)) : "memory")
#define BAR_CMP(g)  asm volatile("bar.sync %0, 128;" :: "r"(1 + (g)) : "memory")
#define BAR_HLP(g)  asm volatile("bar.sync %0, 64;"  :: "r"(6 + (g)) : "memory")

// ---------------------------------------------------------------------------
// Warp-specialized fused ESN kernel. TWO batches per CTA, 384 threads,
// grid = 128 CTAs (<148 SMs -> exactly one CTA per SM, no cross-CTA issue
// contention). SMSP balance: helpers wid 0..3 (one per SMSP), compute
// wid 4..7 = batch0, wid 8..11 = batch1 -> every SMSP: 1 helper + 2 compute
// warps whose 4-cyc-gap chains interleave.
//   helpers (64 thr/batch): 2-step windows — stage x rows (8-deep ring),
//     produce u[2j+4], u[2j+5] (verified ascending-d chains), LDG ~4 steps
//     ahead.
//   compute (128 thr/batch): serial loop — 8-deep LDS head, 128-FMA chain,
//     tanh, STS; BAR_CMP after odd steps, BAR_ALL every 2nd step.
// ---------------------------------------------------------------------------
__global__ __launch_bounds__(384, 1) void esn_fused_kernel(
    const float* __restrict__ x,
    const float* __restrict__ W_in,
    const float* __restrict__ b_in,
    const float* __restrict__ W_res,
    const float* __restrict__ b_res,
    float* __restrict__ X)
{
    __shared__ __align__(16) float st[2][2][N];      // [group][buf][n]
    __shared__ __align__(16) float uring[2][8][N];   // [group][slot][n]
    __shared__ __align__(16) float xb[2][8][D];      // [group][slot][d]

    const int tid = threadIdx.x;
    const int wid = tid >> 5;

    if (wid < 4) {
        // ================= HELPER PATH =================
        const int g    = wid >> 1;                   // batch group 0/1
        const int lane = tid & 63;
        const int b    = 2 * blockIdx.x + g;
        const float* xrow = x + (size_t)b * T * D;

        const int c0 = lane, c1 = lane + 64;
        float win0[D], win1[D];
#pragma unroll
        for (int d = 0; d < D; d++) {
            win0[d] = W_in[d * N + c0];
            win1[d] = W_in[d * N + c1];
        }
        const float bi0 = b_in[c0], bi1 = b_in[c1];

        float (*xbg)[D] = xb[g];
        float (*urg)[N] = uring[g];

        // prologue: stage x rows 0..5, produce u[0..3]
#pragma unroll
        for (int s = 0; s < 6; s++)
            xbg[s][lane] = xrow[(size_t)s * D + lane];
        BAR_HLP(g);
#pragma unroll
        for (int s = 0; s < 4; s++) {
            const float4* xq = reinterpret_cast<const float4*>(xbg[s]);
            float a0 = 0.f, a1 = 0.f;
#pragma unroll
            for (int j = 0; j < D / 4; j++) {
                float4 c = xq[j];
                a0 = __fmaf_rn(c.x, win0[4 * j],     a0);
                a0 = __fmaf_rn(c.y, win0[4 * j + 1], a0);
                a0 = __fmaf_rn(c.z, win0[4 * j + 2], a0);
                a0 = __fmaf_rn(c.w, win0[4 * j + 3], a0);
                a1 = __fmaf_rn(c.x, win1[4 * j],     a1);
                a1 = __fmaf_rn(c.y, win1[4 * j + 1], a1);
                a1 = __fmaf_rn(c.z, win1[4 * j + 2], a1);
                a1 = __fmaf_rn(c.w, win1[4 * j + 3], a1);
            }
            urg[s][c0] = __fadd_rn(a0, bi0);
            urg[s][c1] = __fadd_rn(a1, bi1);
        }
        float r6 = xrow[(size_t)6 * D + lane];
        float r7 = xrow[(size_t)7 * D + lane];

        for (int j = 0; j < T / 2; j++) {
            BAR_ALL(g);                      // window rendezvous (huge slack)
            const int t4 = 2 * j + 4, t5 = 2 * j + 5;
            const int s6 = 2 * j + 6, s7 = 2 * j + 7;
            if (s6 < T) xbg[s6 & 7][lane] = r6;
            if (s7 < T) xbg[s7 & 7][lane] = r7;
            BAR_HLP(g);
#pragma unroll
            for (int h = 0; h < 2; h++) {
                const int tt = h ? t5 : t4;
                if (tt < T) {
                    const float4* xq =
                        reinterpret_cast<const float4*>(xbg[tt & 7]);
                    float a0 = 0.f, a1 = 0.f;
#pragma unroll
                    for (int jj = 0; jj < D / 4; jj++) {
                        float4 c = xq[jj];
                        a0 = __fmaf_rn(c.x, win0[4 * jj],     a0);
                        a0 = __fmaf_rn(c.y, win0[4 * jj + 1], a0);
                        a0 = __fmaf_rn(c.z, win0[4 * jj + 2], a0);
                        a0 = __fmaf_rn(c.w, win0[4 * jj + 3], a0);
                        a1 = __fmaf_rn(c.x, win1[4 * jj],     a1);
                        a1 = __fmaf_rn(c.y, win1[4 * jj + 1], a1);
                        a1 = __fmaf_rn(c.z, win1[4 * jj + 2], a1);
                        a1 = __fmaf_rn(c.w, win1[4 * jj + 3], a1);
                    }
                    urg[tt & 7][c0] = __fadd_rn(a0, bi0);
                    urg[tt & 7][c1] = __fadd_rn(a1, bi1);
                }
            }
            if (s6 + 2 < T) r6 = xrow[(size_t)(s6 + 2) * D + lane];
            if (s7 + 2 < T) r7 = xrow[(size_t)(s7 + 2) * D + lane];
        }
    } else {
        // ================= COMPUTE PATH =================
        const int g = (wid - 4) >> 2;                // batch group 0/1
        const int n = (tid - 128) & (N - 1);
        const int b = 2 * blockIdx.x + g;

        float w[N];
#pragma unroll
        for (int k = 0; k < N; k++) w[k] = W_res[k * N + n];
        const float brv = b_res[n];

        float (*stg)[N] = st[g];
        float (*urg)[N] = uring[g];
        float* xoP = X + (size_t)b * T * N + n;

        BAR_ALL(g);                                  // R_0

        // t = 0 epilogue
        float xv = __fmul_rn(LEAK, tanh_xla(urg[0][n]));
        stg[0][n] = xv;
        xoP[0] = xv;
        float uthis = urg[1][n];
        BAR_CMP(g);

#define STEP(T_IDX, RD_PAR, WR_PAR)                                        \
        {                                                                  \
            const float halfx = __fmul_rn(1.0f - LEAK, xv);                \
            const float4* xp4 =                                            \
                reinterpret_cast<const float4*>(stg[RD_PAR]);              \
            float4 f[8];                                                   \
            _Pragma("unroll")                                              \
            for (int i = 0; i < 8; i++) f[i] = xp4[i];                     \
            float acc = 0.f;                                               \
            _Pragma("unroll")                                              \
            for (int jj = 0; jj < 32; jj++) {                              \
                float4 c = f[0];                                           \
                _Pragma("unroll")                                          \
                for (int i = 0; i < 7; i++) f[i] = f[i + 1];               \
                if (jj < 24) f[7] = xp4[jj + 8];                           \
                acc = __fmaf_rn(c.x, w[4 * jj],     acc);                  \
                acc = __fmaf_rn(c.y, w[4 * jj + 1], acc);                  \
                acc = __fmaf_rn(c.z, w[4 * jj + 2], acc);                  \
                acc = __fmaf_rn(c.w, w[4 * jj + 3], acc);                  \
            }                                                              \
            float arg = __fadd_rn(__fadd_rn(uthis, acc), brv);             \
            float th  = tanh_xla(arg);                                     \
            xv = __fadd_rn(halfx, __fmul_rn(LEAK, th));                    \
            stg[WR_PAR][n] = xv;                                           \
            xoP[(size_t)(T_IDX) * N] = xv;                                 \
            uthis = urg[((T_IDX) + 1) & 7][n];                             \
        }

        // t = 1 (peeled)
        STEP(1, 0, 1)

        for (int j = 1; j < T / 2; j++) {
            BAR_ALL(g);                              // R_j
            const int te = 2 * j;
            STEP(te, 1, 0)                           // even step
            BAR_CMP(g);
            STEP(te + 1, 0, 1)                       // odd step
        }
#undef STEP
    }
}

// ---------------------------------------------------------------------------
extern "C" void kernel_launch(void* const* d_in, const int* in_sizes, int n_in,
                              void* d_out, int out_size)
{
    const float* x     = (const float*)d_in[0];
    const float* W_in  = (const float*)d_in[1];
    const float* b_in  = (const float*)d_in[2];
    const float* W_res = (const float*)d_in[3];
    const float* b_res = (const float*)d_in[4];
    float* X = (float*)d_out;

    esn_fused_kernel<<<B / 2, 384>>>(x, W_in, b_in, W_res, b_res, X);
}